// round 11
// baseline (speedup 1.0000x reference)
#include <cuda_runtime.h>
#include <cstdint>
#include <cstddef>

// Problem constants
#define Gc 64
#define NODESc 511
#define Nc 512          // NODES + 1 (graph token at row 0 of each graph)
#define Hc 768
#define Ec 4096
#define Mc (Gc * Nc)    // 32768 rows
#define NT 5            // distinct source vectors: node_emb[0..3], graph_emb (t=4)
#define RPB 8           // rows per block
#define NBLK (Mc / RPB) // 4096 blocks
#define NPROD (Gc + 256)// 64 counting blocks + 256 projection blocks = 320

// Scratch (device globals; allocation is forbidden). Zero-initialized at load.
__device__ int   g_cnt[Mc * NT];     // per-dst-row counts of source types
__device__ float g_Q[NT * Hc];       // emb5 @ W_l^T
__device__ float g_Pb[NT * Hc];      // emb5 @ W_r^T + b_l  (bias folded in)
__device__ int   g_done;             // producer arrivals (self-resetting)
__device__ int   g_exit;             // exit tickets   (self-resetting)

// ---------------------------------------------------------------------------
// Single fused persistent kernel, blockDim = 192, grid = 4096.
//   Phase P (bid<320 only): produce g_cnt (bid<64) or g_Q/g_Pb (64<=bid<320),
//                           release-arrive on g_done.
//   Phase 1 (all blocks):   write out1 rows (independent of producers).
//   Spin:                   wait g_done == NPROD, acquire.
//   Phase 2 (all blocks):   write out2 rows.
//   Last block to exit resets g_done/g_exit for the next graph replay.
// ---------------------------------------------------------------------------
__global__ __launch_bounds__(192) void fused_kernel(
    const int* __restrict__ nodes,
    const int* __restrict__ edges,
    const float* __restrict__ node_emb,
    const float* __restrict__ graph_emb,
    const float* __restrict__ Wl,
    const float* __restrict__ Wr,
    const float* __restrict__ bl,
    float* __restrict__ out1,
    float* __restrict__ out2) {
    __shared__ union {
        struct { float4 Eb[NT][192]; float4 Pb[NT][192]; } tab;   // 30720 B
        struct { int scnt[Nc * NT]; int stype[Nc]; } cnt;         // 12288 B
    } sm;
    __shared__ float sC[RPB][NT];
    __shared__ int   sT[RPB];

    const int tid = threadIdx.x;
    const int bid = blockIdx.x;

    // ---------------- Producer phase (bids < NPROD) ----------------
    if (bid < Gc) {
        // per-graph edge counting in shared
        const int g = bid;
        #pragma unroll
        for (int i = tid; i < Nc * NT; i += 192) sm.cnt.scnt[i] = 0;
        if (tid == 0) sm.cnt.stype[0] = 4;
        for (int i = tid; i < NODESc; i += 192)
            sm.cnt.stype[i + 1] = __ldg(nodes + g * NODESc + i);
        __syncthreads();

        const int* eg = edges + (size_t)g * 2 * Ec;
        #pragma unroll
        for (int e = tid; e < Ec; e += 192) {
            int src = __ldg(eg + e);
            int dst = __ldg(eg + Ec + e);
            atomicAdd(&sm.cnt.scnt[dst * NT + sm.cnt.stype[src]], 1);
        }
        __syncthreads();

        int4* dst4 = reinterpret_cast<int4*>(g_cnt + (size_t)g * Nc * NT);
        const int4* src4 = reinterpret_cast<const int4*>(sm.cnt.scnt);
        #pragma unroll
        for (int i = tid; i < (Nc * NT) / 4; i += 192)
            dst4[i] = src4[i];
        __threadfence();
        __syncthreads();
        if (tid == 0) atomicAdd(&g_done, 1);
        __syncthreads();    // all threads past scnt reads before smem reuse below
    } else if (bid < NPROD) {
        // Q/Pb projection: 256 blocks * 6 warps = 1536 (matrix, column) tasks
        const int wglob = (bid - Gc) * 6 + (tid >> 5);
        const int lane  = tid & 31;
        const int mtx   = wglob & 1;       // 0: Wl -> Q, 1: Wr -> Pb
        const int n     = wglob >> 1;      // 0..767

        const float4* Wrow = reinterpret_cast<const float4*>((mtx ? Wr : Wl) + (size_t)n * Hc);
        const float4* e4[NT];
        #pragma unroll
        for (int t = 0; t < 4; ++t)
            e4[t] = reinterpret_cast<const float4*>(node_emb + (size_t)t * Hc);
        e4[4] = reinterpret_cast<const float4*>(graph_emb);

        float acc[NT] = {0.f, 0.f, 0.f, 0.f, 0.f};
        #pragma unroll
        for (int k4 = lane; k4 < Hc / 4; k4 += 32) {
            float4 wv = Wrow[k4];
            #pragma unroll
            for (int t = 0; t < NT; ++t) {
                float4 ev = e4[t][k4];
                acc[t] = fmaf(ev.x, wv.x,
                         fmaf(ev.y, wv.y,
                         fmaf(ev.z, wv.z,
                         fmaf(ev.w, wv.w, acc[t]))));
            }
        }
        #pragma unroll
        for (int t = 0; t < NT; ++t)
            #pragma unroll
            for (int off = 16; off; off >>= 1)
                acc[t] += __shfl_xor_sync(0xffffffffu, acc[t], off);

        if (lane == 0) {
            float* dst = mtx ? g_Pb : g_Q;
            float badd = mtx ? __ldg(bl + n) : 0.f;
            #pragma unroll
            for (int t = 0; t < NT; ++t)
                dst[t * Hc + n] = acc[t] + badd;
        }
        __threadfence();
        __syncthreads();
        if (tid == 0) atomicAdd(&g_done, 1);
    }

    // ---------------- Phase 1: out1 (no producer dependency) ----------------
    const int n4 = tid;
    const int row0 = bid * RPB;

    #pragma unroll
    for (int t = 0; t < 4; ++t)
        sm.tab.Eb[t][n4] = reinterpret_cast<const float4*>(node_emb + (size_t)t * Hc)[n4];
    sm.tab.Eb[4][n4] = reinterpret_cast<const float4*>(graph_emb)[n4];
    if (n4 < RPB) {
        int row = row0 + n4;
        int g = row >> 9;
        int i = row & 511;
        sT[n4] = (i == 0) ? 4 : __ldg(nodes + g * NODESc + i - 1);
    }
    __syncthreads();

    {
        float4* o1p = reinterpret_cast<float4*>(out1 + (size_t)row0 * Hc) + n4;
        #pragma unroll
        for (int r = 0; r < RPB; ++r) {
            __stcs(o1p, sm.tab.Eb[sT[r]][n4]);
            o1p += Hc / 4;
        }
    }

    // ---------------- Spin until producers done ----------------
    if (tid == 0) {
        while (atomicAdd(&g_done, 0) < NPROD) __nanosleep(64);
    }
    __syncthreads();
    __threadfence();   // acquire: make producer writes visible to all threads

    // ---------------- Phase 2: out2 ----------------
    #pragma unroll
    for (int t = 0; t < NT; ++t)
        sm.tab.Pb[t][n4] = reinterpret_cast<const float4*>(g_Pb + (size_t)t * Hc)[n4];

    float4 Q[NT];
    #pragma unroll
    for (int t = 0; t < NT; ++t)
        Q[t] = reinterpret_cast<const float4*>(g_Q + (size_t)t * Hc)[n4];

    if (n4 < RPB) {
        int row = row0 + n4;
        const int* cp = g_cnt + (size_t)row * NT;
        float c[NT];
        float deg = 0.f;
        #pragma unroll
        for (int t = 0; t < NT; ++t) { c[t] = (float)__ldg(cp + t); deg += c[t]; }
        float inv = 1.0f / fmaxf(deg, 1.0f);
        #pragma unroll
        for (int t = 0; t < NT; ++t) sC[n4][t] = c[t] * inv;
    }
    __syncthreads();

    {
        float4* o2p = reinterpret_cast<float4*>(out2 + (size_t)row0 * Hc) + n4;
        #pragma unroll
        for (int r = 0; r < RPB; ++r) {
            float c0 = sC[r][0], c1 = sC[r][1], c2 = sC[r][2], c3 = sC[r][3], c4 = sC[r][4];
            float4 o2 = sm.tab.Pb[sT[r]][n4];
            o2.x = fmaf(c0, Q[0].x, fmaf(c1, Q[1].x, fmaf(c2, Q[2].x, fmaf(c3, Q[3].x, fmaf(c4, Q[4].x, o2.x)))));
            o2.y = fmaf(c0, Q[0].y, fmaf(c1, Q[1].y, fmaf(c2, Q[2].y, fmaf(c3, Q[3].y, fmaf(c4, Q[4].y, o2.y)))));
            o2.z = fmaf(c0, Q[0].z, fmaf(c1, Q[1].z, fmaf(c2, Q[2].z, fmaf(c3, Q[3].z, fmaf(c4, Q[4].z, o2.z)))));
            o2.w = fmaf(c0, Q[0].w, fmaf(c1, Q[1].w, fmaf(c2, Q[2].w, fmaf(c3, Q[3].w, fmaf(c4, Q[4].w, o2.w)))));
            __stcs(o2p, o2);
            o2p += Hc / 4;
        }
    }

    // ---------------- Self-reset for deterministic graph replays ----------------
    __syncthreads();
    __threadfence();
    if (tid == 0) {
        int e = atomicAdd(&g_exit, 1);
        if (e == NBLK - 1) {      // last block out: reset flags for next replay
            g_done = 0;
            g_exit = 0;
            __threadfence();
        }
    }
}

// ---------------------------------------------------------------------------
// Launch. Inputs: input_nodes(i32), input_edges(i32), node_emb(f32),
//                 graph_emb(f32), W_l(f32), b_l(f32), W_r(f32)
// d_out: [graph_node_feature | graph_edge_feature]
// ---------------------------------------------------------------------------
extern "C" void kernel_launch(void* const* d_in, const int* in_sizes, int n_in,
                              void* d_out, int out_size) {
    const int*   nodes     = (const int*)d_in[0];
    const int*   edges     = (const int*)d_in[1];
    const float* node_emb  = (const float*)d_in[2];
    const float* graph_emb = (const float*)d_in[3];
    const float* Wl        = (const float*)d_in[4];
    const float* bl        = (const float*)d_in[5];
    const float* Wr        = (const float*)d_in[6];

    float* out1 = (float*)d_out;
    float* out2 = out1 + (size_t)Mc * Hc;

    fused_kernel<<<NBLK, 192>>>(nodes, edges, node_emb, graph_emb,
                                Wl, Wr, bl, out1, out2);
}

// round 12
// speedup vs baseline: 1.1956x; 1.1956x over previous
#include <cuda_runtime.h>
#include <cstdint>
#include <cstddef>

// Problem constants
#define Gc 64
#define NODESc 511
#define Nc 512          // NODES + 1 (graph token at row 0 of each graph)
#define Hc 768
#define Ec 4096
#define Mc (Gc * Nc)    // 32768 rows
#define NT 5            // distinct source vectors: node_emb[0..3], graph_emb (t=4)
#define RPB 16          // rows per block in out_kernel

// Scratch (device globals; allocation is forbidden)
__device__ int   g_cnt[Mc * NT];     // per-dst-row counts of source types
__device__ float g_Q[NT * Hc];       // emb5 @ W_l^T
__device__ float g_Pb[NT * Hc];      // emb5 @ W_r^T + b_l  (bias folded in)

// ---------------------------------------------------------------------------
// Kernel 1 (fused front end), blockDim = 512:
//   blocks [0, 64):      per-graph edge counting in shared memory (8 edges/thr)
//   blocks [64, 64+96):  Q/Pb projection, 16 warps/block, one warp per
//                        (matrix, column) task (1536 tasks total)
// ---------------------------------------------------------------------------
__global__ __launch_bounds__(512) void front_kernel(
    const int* __restrict__ nodes,
    const int* __restrict__ edges,
    const float* __restrict__ node_emb,
    const float* __restrict__ graph_emb,
    const float* __restrict__ Wl,
    const float* __restrict__ Wr,
    const float* __restrict__ bl) {
    __shared__ int scnt[Nc * NT];    // 10 KB counters
    __shared__ int stype[Nc];        // type per node row (row 0 -> 4)

    const int tid = threadIdx.x;

    if (blockIdx.x < Gc) {
        // ---- per-graph counting ----
        const int g = blockIdx.x;

        #pragma unroll
        for (int i = tid; i < Nc * NT; i += 512) scnt[i] = 0;
        if (tid == 0) stype[0] = 4;
        for (int i = tid; i < NODESc; i += 512)
            stype[i + 1] = __ldg(nodes + g * NODESc + i);
        __syncthreads();

        const int* eg = edges + (size_t)g * 2 * Ec;
        #pragma unroll
        for (int e = tid; e < Ec; e += 512) {
            int src = __ldg(eg + e);
            int dst = __ldg(eg + Ec + e);
            atomicAdd(&scnt[dst * NT + stype[src]], 1);
        }
        __syncthreads();

        int4* dst4 = reinterpret_cast<int4*>(g_cnt + (size_t)g * Nc * NT);
        const int4* src4 = reinterpret_cast<const int4*>(scnt);
        #pragma unroll
        for (int i = tid; i < (Nc * NT) / 4; i += 512)
            dst4[i] = src4[i];
        return;
    }

    // ---- Q/Pb projection: warp w handles (matrix = w&1, column n = w>>1) ----
    const int wglob = (blockIdx.x - Gc) * 16 + (tid >> 5);   // 0..1535
    const int lane  = tid & 31;
    const int mtx   = wglob & 1;        // 0: Wl -> Q, 1: Wr -> Pb
    const int n     = wglob >> 1;       // 0..767

    const float4* Wrow = reinterpret_cast<const float4*>((mtx ? Wr : Wl) + (size_t)n * Hc);
    const float4* e4[NT];
    #pragma unroll
    for (int t = 0; t < 4; ++t)
        e4[t] = reinterpret_cast<const float4*>(node_emb + (size_t)t * Hc);
    e4[4] = reinterpret_cast<const float4*>(graph_emb);

    float acc[NT] = {0.f, 0.f, 0.f, 0.f, 0.f};
    #pragma unroll
    for (int k4 = lane; k4 < Hc / 4; k4 += 32) {
        float4 wv = Wrow[k4];
        #pragma unroll
        for (int t = 0; t < NT; ++t) {
            float4 ev = e4[t][k4];
            acc[t] = fmaf(ev.x, wv.x,
                     fmaf(ev.y, wv.y,
                     fmaf(ev.z, wv.z,
                     fmaf(ev.w, wv.w, acc[t]))));
        }
    }
    #pragma unroll
    for (int t = 0; t < NT; ++t)
        #pragma unroll
        for (int off = 16; off; off >>= 1)
            acc[t] += __shfl_xor_sync(0xffffffffu, acc[t], off);

    if (lane == 0) {
        float* dst = mtx ? g_Pb : g_Q;
        float badd = mtx ? __ldg(bl + n) : 0.f;
        #pragma unroll
        for (int t = 0; t < NT; ++t)
            dst[t * Hc + n] = acc[t] + badd;
    }
}

// ---------------------------------------------------------------------------
// Kernel 2: fused gather + output (same store loop as the 35.0us R6 version,
// RPB raised 8 -> 16 to halve per-block table refill traffic).
//   out1[m] = emb5[type(m)]
//   out2[m][n] = sum_t (cnt[m][t]/deg) * Q[t][n] + Pb[type(m)][n]
// ---------------------------------------------------------------------------
__global__ __launch_bounds__(192) void out_kernel(
    const int* __restrict__ nodes,
    const float* __restrict__ node_emb,
    const float* __restrict__ graph_emb,
    float* __restrict__ out1,
    float* __restrict__ out2) {
    __shared__ float4 sEb[NT][192];      // 15 KB
    __shared__ float4 sPb[NT][192];      // 15 KB
    __shared__ float  sC[RPB][NT];       // scaled counts per row
    __shared__ int    sT[RPB];           // row type per row

    const int n4 = threadIdx.x;          // 0..191 column quad
    const int row0 = blockIdx.x * RPB;

    // Stage tables into shared (once per block)
    #pragma unroll
    for (int t = 0; t < NT; ++t)
        sPb[t][n4] = reinterpret_cast<const float4*>(g_Pb + (size_t)t * Hc)[n4];
    #pragma unroll
    for (int t = 0; t < 4; ++t)
        sEb[t][n4] = reinterpret_cast<const float4*>(node_emb + (size_t)t * Hc)[n4];
    sEb[4][n4] = reinterpret_cast<const float4*>(graph_emb)[n4];

    // Q stays in registers (hot every row)
    float4 Q[NT];
    #pragma unroll
    for (int t = 0; t < NT; ++t)
        Q[t] = reinterpret_cast<const float4*>(g_Q + (size_t)t * Hc)[n4];

    // Per-row counts: RPB threads precompute scaled counts + type
    if (n4 < RPB) {
        int row = row0 + n4;
        int g = row >> 9;
        int i = row & 511;
        sT[n4] = (i == 0) ? 4 : __ldg(nodes + g * NODESc + i - 1);
        const int* cp = g_cnt + (size_t)row * NT;
        float c[NT];
        float deg = 0.f;
        #pragma unroll
        for (int t = 0; t < NT; ++t) { c[t] = (float)__ldg(cp + t); deg += c[t]; }
        float inv = 1.0f / fmaxf(deg, 1.0f);
        #pragma unroll
        for (int t = 0; t < NT; ++t) sC[n4][t] = c[t] * inv;
    }
    __syncthreads();

    float4* o1p = reinterpret_cast<float4*>(out1 + (size_t)row0 * Hc) + n4;
    float4* o2p = reinterpret_cast<float4*>(out2 + (size_t)row0 * Hc) + n4;

    #pragma unroll
    for (int r = 0; r < RPB; ++r) {
        int trow = sT[r];
        float c0 = sC[r][0], c1 = sC[r][1], c2 = sC[r][2], c3 = sC[r][3], c4 = sC[r][4];

        float4 o1 = sEb[trow][n4];
        float4 o2 = sPb[trow][n4];
        o2.x = fmaf(c0, Q[0].x, fmaf(c1, Q[1].x, fmaf(c2, Q[2].x, fmaf(c3, Q[3].x, fmaf(c4, Q[4].x, o2.x)))));
        o2.y = fmaf(c0, Q[0].y, fmaf(c1, Q[1].y, fmaf(c2, Q[2].y, fmaf(c3, Q[3].y, fmaf(c4, Q[4].y, o2.y)))));
        o2.z = fmaf(c0, Q[0].z, fmaf(c1, Q[1].z, fmaf(c2, Q[2].z, fmaf(c3, Q[3].z, fmaf(c4, Q[4].z, o2.z)))));
        o2.w = fmaf(c0, Q[0].w, fmaf(c1, Q[1].w, fmaf(c2, Q[2].w, fmaf(c3, Q[3].w, fmaf(c4, Q[4].w, o2.w)))));

        __stcs(o1p, o1);
        __stcs(o2p, o2);
        o1p += Hc / 4;
        o2p += Hc / 4;
    }
}

// ---------------------------------------------------------------------------
// Launch. Inputs: input_nodes(i32), input_edges(i32), node_emb(f32),
//                 graph_emb(f32), W_l(f32), b_l(f32), W_r(f32)
// d_out: [graph_node_feature | graph_edge_feature]
// ---------------------------------------------------------------------------
extern "C" void kernel_launch(void* const* d_in, const int* in_sizes, int n_in,
                              void* d_out, int out_size) {
    const int*   nodes     = (const int*)d_in[0];
    const int*   edges     = (const int*)d_in[1];
    const float* node_emb  = (const float*)d_in[2];
    const float* graph_emb = (const float*)d_in[3];
    const float* Wl        = (const float*)d_in[4];
    const float* bl        = (const float*)d_in[5];
    const float* Wr        = (const float*)d_in[6];

    float* out1 = (float*)d_out;
    float* out2 = out1 + (size_t)Mc * Hc;

    front_kernel<<<Gc + 96, 512>>>(nodes, edges, node_emb, graph_emb, Wl, Wr, bl);
    out_kernel<<<Mc / RPB, Hc / 4>>>(nodes, node_emb, graph_emb, out1, out2);
}

// round 13
// speedup vs baseline: 1.2611x; 1.0548x over previous
#include <cuda_runtime.h>
#include <cstdint>
#include <cstddef>

// Problem constants
#define Gc 64
#define NODESc 511
#define Nc 512          // NODES + 1 (graph token at row 0 of each graph)
#define Hc 768
#define Ec 4096
#define Mc (Gc * Nc)    // 32768 rows
#define NT 5            // distinct source vectors: node_emb[0..3], graph_emb (t=4)

#define RPB_A 16        // rows per out1-writer block in kernelA
#define RPB_B 32        // rows per block in kernelB

#define NBLK_CNT  Gc                 // 64 counting blocks
#define NBLK_PROJ 256                // 256 * 6 warps = 1536 proj tasks
#define NPROD (NBLK_CNT + NBLK_PROJ) // 320
#define NBLK_OUT1 (Mc / RPB_A)       // 2048

// Scratch (device globals; allocation is forbidden)
__device__ int   g_cnt[Mc * NT];     // per-dst-row counts of source types
__device__ float g_Q[NT * Hc];       // emb5 @ W_l^T
__device__ float g_Pb[NT * Hc];      // emb5 @ W_r^T + b_l  (bias folded in)

// ---------------------------------------------------------------------------
// Kernel A, blockDim = 192. Producers first (finish early, hidden behind
// the out1 store stream), then out1 writers:
//   bid [0, 64):        per-graph edge counting in shared memory
//   bid [64, 320):      Q/Pb projection, 6 warps/block, warp per (matrix,col)
//   bid [320, 320+2048): out1 writer, 16 rows/block
// ---------------------------------------------------------------------------
__global__ __launch_bounds__(192) void kernelA(
    const int* __restrict__ nodes,
    const int* __restrict__ edges,
    const float* __restrict__ node_emb,
    const float* __restrict__ graph_emb,
    const float* __restrict__ Wl,
    const float* __restrict__ Wr,
    const float* __restrict__ bl,
    float* __restrict__ out1) {
    const int tid = threadIdx.x;

    if (blockIdx.x < NBLK_CNT) {
        // ---- per-graph counting ----
        __shared__ int scnt[Nc * NT];    // 10 KB
        __shared__ int stype[Nc];
        const int g = blockIdx.x;

        #pragma unroll
        for (int i = tid; i < Nc * NT; i += 192) scnt[i] = 0;
        if (tid == 0) stype[0] = 4;
        for (int i = tid; i < NODESc; i += 192)
            stype[i + 1] = __ldg(nodes + g * NODESc + i);
        __syncthreads();

        const int* eg = edges + (size_t)g * 2 * Ec;
        #pragma unroll
        for (int e = tid; e < Ec; e += 192) {
            int src = __ldg(eg + e);
            int dst = __ldg(eg + Ec + e);
            atomicAdd(&scnt[dst * NT + stype[src]], 1);
        }
        __syncthreads();

        int4* dst4 = reinterpret_cast<int4*>(g_cnt + (size_t)g * Nc * NT);
        const int4* src4 = reinterpret_cast<const int4*>(scnt);
        #pragma unroll
        for (int i = tid; i < (Nc * NT) / 4; i += 192)
            dst4[i] = src4[i];
        return;
    }

    if (blockIdx.x < NPROD) {
        // ---- Q/Pb projection: warp w -> (matrix = w&1, column n = w>>1) ----
        const int wglob = (blockIdx.x - NBLK_CNT) * 6 + (tid >> 5);   // 0..1535
        const int lane  = tid & 31;
        const int mtx   = wglob & 1;        // 0: Wl -> Q, 1: Wr -> Pb
        const int n     = wglob >> 1;       // 0..767

        const float4* Wrow = reinterpret_cast<const float4*>((mtx ? Wr : Wl) + (size_t)n * Hc);
        const float4* e4[NT];
        #pragma unroll
        for (int t = 0; t < 4; ++t)
            e4[t] = reinterpret_cast<const float4*>(node_emb + (size_t)t * Hc);
        e4[4] = reinterpret_cast<const float4*>(graph_emb);

        float acc[NT] = {0.f, 0.f, 0.f, 0.f, 0.f};
        #pragma unroll
        for (int k4 = lane; k4 < Hc / 4; k4 += 32) {
            float4 wv = Wrow[k4];
            #pragma unroll
            for (int t = 0; t < NT; ++t) {
                float4 ev = e4[t][k4];
                acc[t] = fmaf(ev.x, wv.x,
                         fmaf(ev.y, wv.y,
                         fmaf(ev.z, wv.z,
                         fmaf(ev.w, wv.w, acc[t]))));
            }
        }
        #pragma unroll
        for (int t = 0; t < NT; ++t)
            #pragma unroll
            for (int off = 16; off; off >>= 1)
                acc[t] += __shfl_xor_sync(0xffffffffu, acc[t], off);

        if (lane == 0) {
            float* dst = mtx ? g_Pb : g_Q;
            float badd = mtx ? __ldg(bl + n) : 0.f;
            #pragma unroll
            for (int t = 0; t < NT; ++t)
                dst[t * Hc + n] = acc[t] + badd;
        }
        return;
    }

    // ---- out1 writer: 16 rows, out1[row] = emb5[type(row)] ----
    __shared__ float4 sEb[NT][192];
    __shared__ int    sT[RPB_A];
    const int n4 = tid;
    const int row0 = (blockIdx.x - NPROD) * RPB_A;

    #pragma unroll
    for (int t = 0; t < 4; ++t)
        sEb[t][n4] = reinterpret_cast<const float4*>(node_emb + (size_t)t * Hc)[n4];
    sEb[4][n4] = reinterpret_cast<const float4*>(graph_emb)[n4];
    if (n4 < RPB_A) {
        int row = row0 + n4;
        int g = row >> 9;
        int i = row & 511;
        sT[n4] = (i == 0) ? 4 : __ldg(nodes + g * NODESc + i - 1);
    }
    __syncthreads();

    float4* o1p = reinterpret_cast<float4*>(out1 + (size_t)row0 * Hc) + n4;
    #pragma unroll
    for (int r = 0; r < RPB_A; ++r) {
        __stcs(o1p, sEb[sT[r]][n4]);
        o1p += Hc / 4;
    }
}

// ---------------------------------------------------------------------------
// Kernel B: out2 only, 32 rows/block.
//   out2[m][n] = sum_t (cnt[m][t]/deg) * Q[t][n] + Pb[type(m)][n]
// Q in registers, Pb in shared (indexed by row type), scaled counts in shared.
// 32 independent STG.128 per thread; table staging amortized over 32 rows.
// ---------------------------------------------------------------------------
__global__ __launch_bounds__(192) void kernelB(
    const int* __restrict__ nodes,
    float* __restrict__ out2) {
    __shared__ float4 sPb[NT][192];      // 15 KB
    __shared__ float  sC[RPB_B][NT];
    __shared__ int    sT[RPB_B];

    const int n4 = threadIdx.x;
    const int row0 = blockIdx.x * RPB_B;

    #pragma unroll
    for (int t = 0; t < NT; ++t)
        sPb[t][n4] = reinterpret_cast<const float4*>(g_Pb + (size_t)t * Hc)[n4];

    float4 Q[NT];
    #pragma unroll
    for (int t = 0; t < NT; ++t)
        Q[t] = reinterpret_cast<const float4*>(g_Q + (size_t)t * Hc)[n4];

    if (n4 < RPB_B) {
        int row = row0 + n4;
        int g = row >> 9;
        int i = row & 511;
        sT[n4] = (i == 0) ? 4 : __ldg(nodes + g * NODESc + i - 1);
        const int* cp = g_cnt + (size_t)row * NT;
        float c[NT];
        float deg = 0.f;
        #pragma unroll
        for (int t = 0; t < NT; ++t) { c[t] = (float)__ldg(cp + t); deg += c[t]; }
        float inv = 1.0f / fmaxf(deg, 1.0f);
        #pragma unroll
        for (int t = 0; t < NT; ++t) sC[n4][t] = c[t] * inv;
    }
    __syncthreads();

    float4* o2p = reinterpret_cast<float4*>(out2 + (size_t)row0 * Hc) + n4;
    #pragma unroll
    for (int r = 0; r < RPB_B; ++r) {
        float c0 = sC[r][0], c1 = sC[r][1], c2 = sC[r][2], c3 = sC[r][3], c4 = sC[r][4];
        float4 o2 = sPb[sT[r]][n4];
        o2.x = fmaf(c0, Q[0].x, fmaf(c1, Q[1].x, fmaf(c2, Q[2].x, fmaf(c3, Q[3].x, fmaf(c4, Q[4].x, o2.x)))));
        o2.y = fmaf(c0, Q[0].y, fmaf(c1, Q[1].y, fmaf(c2, Q[2].y, fmaf(c3, Q[3].y, fmaf(c4, Q[4].y, o2.y)))));
        o2.z = fmaf(c0, Q[0].z, fmaf(c1, Q[1].z, fmaf(c2, Q[2].z, fmaf(c3, Q[3].z, fmaf(c4, Q[4].z, o2.z)))));
        o2.w = fmaf(c0, Q[0].w, fmaf(c1, Q[1].w, fmaf(c2, Q[2].w, fmaf(c3, Q[3].w, fmaf(c4, Q[4].w, o2.w)))));
        __stcs(o2p, o2);
        o2p += Hc / 4;
    }
}

// ---------------------------------------------------------------------------
// Launch. Inputs: input_nodes(i32), input_edges(i32), node_emb(f32),
//                 graph_emb(f32), W_l(f32), b_l(f32), W_r(f32)
// d_out: [graph_node_feature | graph_edge_feature]
// ---------------------------------------------------------------------------
extern "C" void kernel_launch(void* const* d_in, const int* in_sizes, int n_in,
                              void* d_out, int out_size) {
    const int*   nodes     = (const int*)d_in[0];
    const int*   edges     = (const int*)d_in[1];
    const float* node_emb  = (const float*)d_in[2];
    const float* graph_emb = (const float*)d_in[3];
    const float* Wl        = (const float*)d_in[4];
    const float* bl        = (const float*)d_in[5];
    const float* Wr        = (const float*)d_in[6];

    float* out1 = (float*)d_out;
    float* out2 = out1 + (size_t)Mc * Hc;

    kernelA<<<NPROD + NBLK_OUT1, 192>>>(nodes, edges, node_emb, graph_emb,
                                        Wl, Wr, bl, out1);
    kernelB<<<Mc / RPB_B, 192>>>(nodes, out2);
}